// round 14
// baseline (speedup 1.0000x reference)
#include <cuda_runtime.h>
#include <cstdint>

#define B 16
#define CIN 16
#define DD 16
#define HH 128
#define WW 128
#define COUT 64
#define HW (HH*WW)

// ---- device scratch ----
__device__ float g_s[B*CIN*HW];            // depth-summed x
__device__ uint2 g_wb2[3*3*64*24];         // weight bf16x2 (hi,lo) [kh][kw][co][kpair]

// pack two floats into bf16x2 (x -> low half, y -> high half), round-nearest
__device__ __forceinline__ uint32_t pack2(float lo, float hi){
    uint32_t r; asm("cvt.rn.bf16x2.f32 %0, %1, %2;" : "=r"(r) : "f"(hi), "f"(lo)); return r;
}
// 2-term bf16 split of an adjacent-k float2 pair
__device__ __forceinline__ void split2(float2 p, uint32_t& h, uint32_t& l){
    h = pack2(p.x, p.y);
    float he = __uint_as_float(h << 16);
    float ho = __uint_as_float(h & 0xFFFF0000u);
    l = pack2(p.x - he, p.y - ho);
}

// m16n8k16 row.col bf16 MMA, accumulate in place
__device__ __forceinline__ void mma16(float* d,
                                      uint32_t a0, uint32_t a1, uint32_t a2, uint32_t a3,
                                      uint32_t b0, uint32_t b1){
    asm("mma.sync.aligned.m16n8k16.row.col.f32.bf16.bf16.f32 "
        "{%0,%1,%2,%3},{%4,%5,%6,%7},{%8,%9},{%0,%1,%2,%3};"
        : "+f"(d[0]), "+f"(d[1]), "+f"(d[2]), "+f"(d[3])
        : "r"(a0), "r"(a1), "r"(a2), "r"(a3), "r"(b0), "r"(b1));
}

// ============================================================
// Kernel A: depth sum + weight bf16 (hi,lo) prep (merged)
// ============================================================
#define DS_BLOCKS (B*CIN*(HW/4)/256)      // 8192
#define NWPAIR (3*3*64*24)                // 13824
__global__ void prep_all(const float* __restrict__ x,
                         const float* __restrict__ wsum,
                         const float* __restrict__ wfront,
                         const float* __restrict__ wback) {
    int bid = blockIdx.x;
    int tid = threadIdx.x;
    if (bid < DS_BLOCKS) {
        int i = bid*256 + tid;
        int bc = i / (HW/4);
        int r  = i - bc*(HW/4);
        const float4* p = reinterpret_cast<const float4*>(x) + (size_t)bc*DD*(HW/4) + r;
        float4 acc = p[0];
        #pragma unroll
        for (int z = 1; z < DD; z++) {
            float4 v = p[(size_t)z*(HW/4)];
            acc.x += v.x; acc.y += v.y; acc.z += v.z; acc.w += v.w;
        }
        reinterpret_cast<float4*>(g_s)[(size_t)bc*(HW/4) + r] = acc;
    } else {
        int idx = (bid - DS_BLOCKS)*256 + tid;
        if (idx < NWPAIR) {
            int kp = idx % 24;
            int co = (idx / 24) & 63;
            int kw = (idx / (24*64)) % 3;
            int kh = idx / (24*64*3);
            float vp[2];
            #pragma unroll
            for (int j = 0; j < 2; j++) {
                int ci = 2*kp + j;
                int grp = ci >> 4, ch = ci & 15;
                const float* src = grp==0 ? wsum : (grp==1 ? wfront : wback);
                float v = src[(co*CIN + ch)*9 + kh*3 + kw];
                vp[j] = grp ? -v : v;
            }
            uint32_t hh, ll;
            split2(make_float2(vp[0], vp[1]), hh, ll);
            g_wb2[idx] = make_uint2(hh, ll);
        }
    }
}

// ============================================================
// Kernel B: 3-product bf16 implicit conv + softmax + tanh
//   CTA = image row (b,h): M=128 px, N=64 co. 256 threads, 8 warps, 3 CTAs/SM.
//   Warp tile M32 x N32: mg = wid&3, nh = wid>>2.
//   (hi,lo) INTERLEAVED as uint2 -> every fragment pair = ONE LDS.64.
//   u2 pitch 28: per 16-lane phase bank = (28g+c) mod 16 = {0,12,8,4}+c
//   -> 16 distinct 8B banks, conflict-free.
//   smem (floats):
//     [0,64)            bias
//     [64, +10752)      B2: [kw3][co64][kpair24 pad28] uint2 (hi,lo)
//     [10816, +7280)    A2: [col130][kpair24 pad28] uint2 (hi,lo)
//     logits alias B region after MMAs: [px128][co] pitch 68 (8704 <= 10752)
// ============================================================
#define KP 24
#define PP 28                       // pitch in uint2
#define SB_KW (64*PP)               // 1792 u2 per kw
#define OFF_B 64                    // float offset (256B aligned)
#define OFF_A (OFF_B + 3*SB_KW*2)   // 10816
#define LP 68
#define SMEM_FLOATS (OFF_A + 130*PP*2)  // 18096
#define SMEM_BYTES (SMEM_FLOATS*4)      // 72384

__global__ void __launch_bounds__(256, 3)
conv_mma(const float* __restrict__ x,
         const float* __restrict__ bias,
         float* __restrict__ out) {
    extern __shared__ float sm[];
    float* sbias = sm;
    uint2* sB2   = reinterpret_cast<uint2*>(sm + OFF_B);
    uint2* sA2   = reinterpret_cast<uint2*>(sm + OFF_A);
    float* LG    = sm + OFF_B;       // logits alias (B region dead after MMAs)

    const int tid = threadIdx.x;
    const int h = blockIdx.x;
    const int b = blockIdx.y;

    if (tid < 64) sbias[tid] = bias[tid];

    const int lane = tid & 31, wid = tid >> 5;
    const int g = lane >> 2, c = lane & 3;
    const int mg = wid & 3, nh = wid >> 2;

    float C[2][4][4];
    #pragma unroll
    for (int m = 0; m < 2; m++)
        #pragma unroll
        for (int nt = 0; nt < 4; nt++)
            #pragma unroll
            for (int r = 0; r < 4; r++) C[m][nt][r] = 0.0f;

    for (int kh = 0; kh < 3; kh++) {
        const int row = h + kh - 1;
        const bool valid = (unsigned)row < HH;

        // ---- build A plane: split at build time, (hi,lo) interleaved ----
        const float* ps = g_s + (size_t)b*CIN*HW + (size_t)row*WW;
        const float* pf = x  + (size_t)b*CIN*DD*HW + (size_t)row*WW;
        for (int i = tid; i < KP*130; i += 256) {
            int kp = i / 130, r = i - kp*130;
            int col = r - 1;
            float va = 0.0f, vb = 0.0f;
            if (valid && (unsigned)col < WW) {
                #pragma unroll
                for (int j = 0; j < 2; j++) {
                    int ci = 2*kp + j;
                    int grp = ci >> 4, ch = ci & 15;
                    const float* src = (grp == 0) ? ps + (size_t)ch*HW
                                     : pf + ((size_t)ch*DD + (grp == 1 ? 0 : DD-1))*HW;
                    float v = __ldg(src + col);
                    if (j == 0) va = v; else vb = v;
                }
            }
            uint32_t hh, ll;
            split2(make_float2(va, vb), hh, ll);
            sA2[r*PP + kp] = make_uint2(hh, ll);
        }
        // ---- stage B plane (pre-split uint2 in gmem) ----
        {
            const uint2* wsrc = g_wb2 + (size_t)kh*3*64*KP;
            for (int i = tid; i < 3*64*KP; i += 256) {
                int kp = i % KP;
                int co = (i / KP) & 63;
                int kw = i / (KP*64);
                sB2[kw*SB_KW + co*PP + kp] = __ldg(wsrc + i);
            }
        }
        __syncthreads();

        #pragma unroll
        for (int kw = 0; kw < 3; kw++) {
            const uint2* aP = sA2 + (mg*32 + kw + g)*PP + c;
            const uint2* bP = sB2 + kw*SB_KW + (nh*32 + g)*PP + c;
            #pragma unroll
            for (int ks = 0; ks < 3; ks++) {
                const int k0 = ks*8;   // kpair offset
                // ---- A fragments: 8 LDS.64 (hi,lo together) ----
                uint2 qa[2][4];
                #pragma unroll
                for (int m = 0; m < 2; m++) {
                    qa[m][0] = aP[(m*16    )*PP + k0    ];
                    qa[m][1] = aP[(m*16 + 8)*PP + k0    ];
                    qa[m][2] = aP[(m*16    )*PP + k0 + 4];
                    qa[m][3] = aP[(m*16 + 8)*PP + k0 + 4];
                }
                // ---- B fragments: 8 LDS.64 ----
                uint2 qb[4][2];
                #pragma unroll
                for (int nt = 0; nt < 4; nt++) {
                    qb[nt][0] = bP[nt*8*PP + k0];
                    qb[nt][1] = bP[nt*8*PP + k0 + 4];
                }
                // ---- term-major MMAs ----
                #pragma unroll
                for (int nt = 0; nt < 4; nt++) {          // Ahi * Bhi
                    mma16(C[0][nt], qa[0][0].x, qa[0][1].x, qa[0][2].x, qa[0][3].x, qb[nt][0].x, qb[nt][1].x);
                    mma16(C[1][nt], qa[1][0].x, qa[1][1].x, qa[1][2].x, qa[1][3].x, qb[nt][0].x, qb[nt][1].x);
                }
                #pragma unroll
                for (int nt = 0; nt < 4; nt++) {          // Ahi * Blo
                    mma16(C[0][nt], qa[0][0].x, qa[0][1].x, qa[0][2].x, qa[0][3].x, qb[nt][0].y, qb[nt][1].y);
                    mma16(C[1][nt], qa[1][0].x, qa[1][1].x, qa[1][2].x, qa[1][3].x, qb[nt][0].y, qb[nt][1].y);
                }
                #pragma unroll
                for (int nt = 0; nt < 4; nt++) {          // Alo * Bhi
                    mma16(C[0][nt], qa[0][0].y, qa[0][1].y, qa[0][2].y, qa[0][3].y, qb[nt][0].x, qb[nt][1].x);
                    mma16(C[1][nt], qa[1][0].y, qa[1][1].y, qa[1][2].y, qa[1][3].y, qb[nt][0].x, qb[nt][1].x);
                }
            }
        }
        __syncthreads();
    }

    // ---- write logits (single plane; each output owned by one warp) ----
    #pragma unroll
    for (int m = 0; m < 2; m++) {
        int px0 = mg*32 + m*16 + g;
        #pragma unroll
        for (int nt = 0; nt < 4; nt++) {
            int colb = nh*32 + nt*8 + 2*c;
            *reinterpret_cast<float2*>(LG + px0*LP + colb)     = make_float2(C[m][nt][0], C[m][nt][1]);
            *reinterpret_cast<float2*>(LG + (px0+8)*LP + colb) = make_float2(C[m][nt][2], C[m][nt][3]);
        }
    }
    __syncthreads();

    // ---- softmax + tanh: 2 threads/pixel, shfl combine ----
    const int px = tid >> 1;
    const int hf = tid & 1;
    const float* l0p = LG + px*LP + (hf << 5);
    const float* mb  = sbias + (hf << 5);

    float ev[32];
    float mx = -3.4e38f;
    #pragma unroll
    for (int i = 0; i < 32; i++) {
        float v = l0p[i] + mb[i];
        ev[i] = v;
        mx = fmaxf(mx, v);
    }
    mx = fmaxf(mx, __shfl_xor_sync(0xFFFFFFFFu, mx, 1));
    float s = 0.0f;
    #pragma unroll
    for (int i = 0; i < 32; i++) {
        float e = __expf(ev[i] - mx);
        ev[i] = e;
        s += e;
    }
    s += __shfl_xor_sync(0xFFFFFFFFu, s, 1);
    float inv = __fdividef(1.0f, s);

    float* ob = out + (size_t)b*COUT*HW + (size_t)h*WW + px + (size_t)(hf << 5)*HW;
    #pragma unroll
    for (int i = 0; i < 32; i++) {
        float p = ev[i] * inv;
        float t = __expf(-2.0f * p);
        ob[(size_t)i*HW] = __fdividef(1.0f - t, 1.0f + t);
    }
}

// ============================================================
extern "C" void kernel_launch(void* const* d_in, const int* in_sizes, int n_in,
                              void* d_out, int out_size) {
    const float* x      = (const float*)d_in[0];
    const float* wsum   = (const float*)d_in[1];
    const float* wfront = (const float*)d_in[2];
    const float* wback  = (const float*)d_in[3];
    const float* bias   = (const float*)d_in[4];
    float* out = (float*)d_out;

    cudaFuncSetAttribute(conv_mma, cudaFuncAttributeMaxDynamicSharedMemorySize, SMEM_BYTES);

    prep_all<<<DS_BLOCKS + (NWPAIR + 255)/256, 256>>>(x, wsum, wfront, wback);
    dim3 grid(HH, B);
    conv_mma<<<grid, 256, SMEM_BYTES>>>(x, bias, out);
}

// round 15
// speedup vs baseline: 1.2223x; 1.2223x over previous
#include <cuda_runtime.h>
#include <cstdint>

#define B 16
#define CIN 16
#define DD 16
#define HH 128
#define WW 128
#define COUT 64
#define HW (HH*WW)

// ---- device scratch ----
__device__ float g_s[B*CIN*HW];            // depth-summed x
__device__ uint32_t g_wbh[3*3*64*24];      // weight bf16x2 hi [kh][kw][co][kpair]
__device__ uint32_t g_wbl[3*3*64*24];      // weight bf16x2 lo

// pack two floats into bf16x2 (x -> low half, y -> high half), round-nearest
__device__ __forceinline__ uint32_t pack2(float lo, float hi){
    uint32_t r; asm("cvt.rn.bf16x2.f32 %0, %1, %2;" : "=r"(r) : "f"(hi), "f"(lo)); return r;
}
// 2-term bf16 split of an adjacent-k float2 pair
__device__ __forceinline__ void split2(float2 p, uint32_t& h, uint32_t& l){
    h = pack2(p.x, p.y);
    float he = __uint_as_float(h << 16);
    float ho = __uint_as_float(h & 0xFFFF0000u);
    l = pack2(p.x - he, p.y - ho);
}

// m16n8k16 row.col bf16 MMA, accumulate in place
__device__ __forceinline__ void mma16(float* d,
                                      uint32_t a0, uint32_t a1, uint32_t a2, uint32_t a3,
                                      uint32_t b0, uint32_t b1){
    asm("mma.sync.aligned.m16n8k16.row.col.f32.bf16.bf16.f32 "
        "{%0,%1,%2,%3},{%4,%5,%6,%7},{%8,%9},{%0,%1,%2,%3};"
        : "+f"(d[0]), "+f"(d[1]), "+f"(d[2]), "+f"(d[3])
        : "r"(a0), "r"(a1), "r"(a2), "r"(a3), "r"(b0), "r"(b1));
}

// ============================================================
// Kernel A: depth sum + weight bf16 hi/lo prep (merged)
// ============================================================
#define DS_BLOCKS (B*CIN*(HW/4)/256)      // 8192
#define NWPAIR (3*3*64*24)                // 13824
__global__ void prep_all(const float* __restrict__ x,
                         const float* __restrict__ wsum,
                         const float* __restrict__ wfront,
                         const float* __restrict__ wback) {
    int bid = blockIdx.x;
    int tid = threadIdx.x;
    if (bid < DS_BLOCKS) {
        int i = bid*256 + tid;
        int bc = i / (HW/4);
        int r  = i - bc*(HW/4);
        const float4* p = reinterpret_cast<const float4*>(x) + (size_t)bc*DD*(HW/4) + r;
        float4 acc = p[0];
        #pragma unroll
        for (int z = 1; z < DD; z++) {
            float4 v = p[(size_t)z*(HW/4)];
            acc.x += v.x; acc.y += v.y; acc.z += v.z; acc.w += v.w;
        }
        reinterpret_cast<float4*>(g_s)[(size_t)bc*(HW/4) + r] = acc;
    } else {
        int idx = (bid - DS_BLOCKS)*256 + tid;
        if (idx < NWPAIR) {
            int kp = idx % 24;
            int co = (idx / 24) & 63;
            int kw = (idx / (24*64)) % 3;
            int kh = idx / (24*64*3);
            float vp[2];
            #pragma unroll
            for (int j = 0; j < 2; j++) {
                int ci = 2*kp + j;
                int grp = ci >> 4, ch = ci & 15;
                const float* src = grp==0 ? wsum : (grp==1 ? wfront : wback);
                float v = src[(co*CIN + ch)*9 + kh*3 + kw];
                vp[j] = grp ? -v : v;
            }
            uint32_t hh, ll;
            split2(make_float2(vp[0], vp[1]), hh, ll);
            g_wbh[idx] = hh;
            g_wbl[idx] = ll;
        }
    }
}

// ============================================================
// Kernel B: 3-product bf16 implicit conv + softmax + tanh
//   CTA = TWO image rows (b, 2h..2h+1): M=256 px, N=64 co.
//   512 threads, 16 warps, 2 CTAs/SM -> 8 warps/SMSP.
//   Warp tile M32 x N32: mg = wid&7 (px 32*mg..+32), nh = wid>>3.
//   Separate hi/lo bf16x2 planes (LDS.32, R13 scheme), pitch 28:
//   bank (28g+c) mod 32 distinct -> conflict-free.
//   B fragments loaded per-nt (4 live regs) to fit 64-reg budget.
//   smem (floats):
//     [0,64)            bias
//     [64, +5376)       B hi: [kw3][co64][kp24 pad28]
//     [5440, +5376)     B lo
//     [10816, +7280)    A hi: [pxr2][col130][kp24 pad28]  (per kh)
//     [18096, +7280)    A lo
//     logits alias from 64: [px256][co] pitch 68 (17408 <= 25312)
// ============================================================
#define KP 24
#define PP 28
#define SB_KW (64*PP)              // 1792
#define OFF_BH 64
#define OFF_BL (OFF_BH + 3*SB_KW)  // 5440
#define OFF_AH (OFF_BL + 3*SB_KW)  // 10816
#define APL (130*PP)               // 3640 per pixel-row
#define OFF_AL (OFF_AH + 2*APL)    // 18096
#define LP 68
#define SMEM_FLOATS (OFF_AL + 2*APL)   // 25376
#define SMEM_BYTES (SMEM_FLOATS*4)     // 101504

__global__ void __launch_bounds__(512, 2)
conv_mma(const float* __restrict__ x,
         const float* __restrict__ bias,
         float* __restrict__ out) {
    extern __shared__ float sm[];
    float* sbias   = sm;
    uint32_t* sBH  = reinterpret_cast<uint32_t*>(sm + OFF_BH);
    uint32_t* sBL  = reinterpret_cast<uint32_t*>(sm + OFF_BL);
    uint32_t* sAH  = reinterpret_cast<uint32_t*>(sm + OFF_AH);
    uint32_t* sAL  = reinterpret_cast<uint32_t*>(sm + OFF_AL);
    float* LG      = sm + OFF_BH;    // logits alias

    const int tid = threadIdx.x;
    const int h2 = blockIdx.x;       // row pair: image rows 2*h2, 2*h2+1
    const int b = blockIdx.y;

    if (tid < 64) sbias[tid] = bias[tid];

    const int lane = tid & 31, wid = tid >> 5;
    const int g = lane >> 2, c = lane & 3;
    const int mg = wid & 7, nh = wid >> 3;
    const int pxr = mg >> 2;               // pixel row within pair (0/1)
    const int colbase = (mg & 3) << 5;     // 0,32,64,96

    float C[2][4][4];
    #pragma unroll
    for (int m = 0; m < 2; m++)
        #pragma unroll
        for (int nt = 0; nt < 4; nt++)
            #pragma unroll
            for (int r = 0; r < 4; r++) C[m][nt][r] = 0.0f;

    for (int kh = 0; kh < 3; kh++) {
        // ---- build A planes for both pixel rows at this kh ----
        const float* ps = g_s + (size_t)b*CIN*HW;
        const float* pf = x  + (size_t)b*CIN*DD*HW;
        for (int i = tid; i < KP*260; i += 512) {
            int kp = i / 260;
            int rr = i - kp*260;
            int p = rr / 130, col = rr - p*130 - 1;
            int irow = 2*h2 + p + kh - 1;
            float va = 0.0f, vb = 0.0f;
            if ((unsigned)irow < HH && (unsigned)col < WW) {
                #pragma unroll
                for (int j = 0; j < 2; j++) {
                    int ci = 2*kp + j;
                    int grp = ci >> 4, ch = ci & 15;
                    const float* src = (grp == 0) ? ps + (size_t)ch*HW
                                     : pf + ((size_t)ch*DD + (grp == 1 ? 0 : DD-1))*HW;
                    float v = __ldg(src + irow*WW + col);
                    if (j == 0) va = v; else vb = v;
                }
            }
            uint32_t hh, ll;
            split2(make_float2(va, vb), hh, ll);
            int d = p*APL + (rr - p*130)*PP + kp;
            sAH[d] = hh;
            sAL[d] = ll;
        }
        // ---- stage B planes (pre-split in gmem) ----
        {
            const uint32_t* wh = g_wbh + (size_t)kh*3*64*KP;
            const uint32_t* wl = g_wbl + (size_t)kh*3*64*KP;
            for (int i = tid; i < 3*64*KP; i += 512) {
                int kp = i % KP;
                int co = (i / KP) & 63;
                int kw = i / (KP*64);
                int d = kw*SB_KW + co*PP + kp;
                sBH[d] = __ldg(wh + i);
                sBL[d] = __ldg(wl + i);
            }
        }
        __syncthreads();

        #pragma unroll
        for (int kw = 0; kw < 3; kw++) {
            const uint32_t* aH = sAH + pxr*APL + (colbase + kw + g)*PP + c;
            const uint32_t* aL = sAL + pxr*APL + (colbase + kw + g)*PP + c;
            const uint32_t* bH = sBH + kw*SB_KW + (nh*32 + g)*PP + c;
            const uint32_t* bL = sBL + kw*SB_KW + (nh*32 + g)*PP + c;
            #pragma unroll
            for (int ks = 0; ks < 3; ks++) {
                const int k0 = ks*8;
                // ---- A fragments (LDS.32) ----
                uint32_t ah[2][4], al[2][4];
                #pragma unroll
                for (int m = 0; m < 2; m++) {
                    ah[m][0] = aH[(m*16    )*PP + k0    ];
                    ah[m][1] = aH[(m*16 + 8)*PP + k0    ];
                    ah[m][2] = aH[(m*16    )*PP + k0 + 4];
                    ah[m][3] = aH[(m*16 + 8)*PP + k0 + 4];
                    al[m][0] = aL[(m*16    )*PP + k0    ];
                    al[m][1] = aL[(m*16 + 8)*PP + k0    ];
                    al[m][2] = aL[(m*16    )*PP + k0 + 4];
                    al[m][3] = aL[(m*16 + 8)*PP + k0 + 4];
                }
                // ---- per-nt B load (4 live regs) + 6 MMAs ----
                #pragma unroll
                for (int nt = 0; nt < 4; nt++) {
                    uint32_t bh0 = bH[nt*8*PP + k0];
                    uint32_t bh1 = bH[nt*8*PP + k0 + 4];
                    uint32_t bl0 = bL[nt*8*PP + k0];
                    uint32_t bl1 = bL[nt*8*PP + k0 + 4];
                    mma16(C[0][nt], ah[0][0], ah[0][1], ah[0][2], ah[0][3], bh0, bh1);
                    mma16(C[1][nt], ah[1][0], ah[1][1], ah[1][2], ah[1][3], bh0, bh1);
                    mma16(C[0][nt], ah[0][0], ah[0][1], ah[0][2], ah[0][3], bl0, bl1);
                    mma16(C[1][nt], ah[1][0], ah[1][1], ah[1][2], ah[1][3], bl0, bl1);
                    mma16(C[0][nt], al[0][0], al[0][1], al[0][2], al[0][3], bh0, bh1);
                    mma16(C[1][nt], al[1][0], al[1][1], al[1][2], al[1][3], bh0, bh1);
                }
            }
        }
        __syncthreads();
    }

    // ---- write logits (single plane; each output owned by one warp) ----
    #pragma unroll
    for (int m = 0; m < 2; m++) {
        int px0 = mg*32 + m*16 + g;
        #pragma unroll
        for (int nt = 0; nt < 4; nt++) {
            int colb = nh*32 + nt*8 + 2*c;
            *reinterpret_cast<float2*>(LG + px0*LP + colb)     = make_float2(C[m][nt][0], C[m][nt][1]);
            *reinterpret_cast<float2*>(LG + (px0+8)*LP + colb) = make_float2(C[m][nt][2], C[m][nt][3]);
        }
    }
    __syncthreads();

    // ---- softmax + tanh: 2 threads/pixel (512 thr = 256 px) ----
    const int px = tid >> 1;             // 0..255: r = px>>7, col = px&127
    const int hf = tid & 1;
    const float* l0p = LG + px*LP + (hf << 5);
    const float* mb  = sbias + (hf << 5);

    float ev[32];
    float mx = -3.4e38f;
    #pragma unroll
    for (int i = 0; i < 32; i++) {
        float v = l0p[i] + mb[i];
        ev[i] = v;
        mx = fmaxf(mx, v);
    }
    mx = fmaxf(mx, __shfl_xor_sync(0xFFFFFFFFu, mx, 1));
    float s = 0.0f;
    #pragma unroll
    for (int i = 0; i < 32; i++) {
        float e = __expf(ev[i] - mx);
        ev[i] = e;
        s += e;
    }
    s += __shfl_xor_sync(0xFFFFFFFFu, s, 1);
    float inv = __fdividef(1.0f, s);

    int orow = 2*h2 + (px >> 7);
    int ocol = px & 127;
    float* ob = out + (size_t)b*COUT*HW + (size_t)orow*WW + ocol + (size_t)(hf << 5)*HW;
    #pragma unroll
    for (int i = 0; i < 32; i++) {
        float p = ev[i] * inv;
        float t = __expf(-2.0f * p);
        ob[(size_t)i*HW] = __fdividef(1.0f - t, 1.0f + t);
    }
}

// ============================================================
extern "C" void kernel_launch(void* const* d_in, const int* in_sizes, int n_in,
                              void* d_out, int out_size) {
    const float* x      = (const float*)d_in[0];
    const float* wsum   = (const float*)d_in[1];
    const float* wfront = (const float*)d_in[2];
    const float* wback  = (const float*)d_in[3];
    const float* bias   = (const float*)d_in[4];
    float* out = (float*)d_out;

    cudaFuncSetAttribute(conv_mma, cudaFuncAttributeMaxDynamicSharedMemorySize, SMEM_BYTES);

    prep_all<<<DS_BLOCKS + (NWPAIR + 255)/256, 256>>>(x, wsum, wfront, wback);
    dim3 grid(HH/2, B);
    conv_mma<<<grid, 512, SMEM_BYTES>>>(x, bias, out);
}